// round 1
// baseline (speedup 1.0000x reference)
#include <cuda_runtime.h>
#include <cstdint>

#define D_BINS 59
#define C_CH   80
#define O_TOT  139
#define WSROW  148   // padded smem row for weights (multiple of 4, gcd(148,32)=4)
#define B_     4
#define N_     6
#define CIN    256
#define H_     16
#define W_     44
#define HW     704              // H_*W_
#define NPIX   (B_*N_*H_*W_)    // 16896
#define NPT    (NPIX*D_BINS)    // 996864
#define BEV_HW 16384
#define BEVW   128

// ---- device scratch (no allocations allowed) ----
__device__ float  g_depth[NPT];               // [pixel][d]    ~4.0 MB
__device__ float  g_ctx[NPIX*C_CH];           // [pixel][c]    ~5.4 MB
__device__ float4 g_bev[B_*BEV_HW*(C_CH/4)];  // [b][y][x][c4] ~21 MB (L2-resident)

// ============================================================================
// K1: fused 1x1 conv (139x44x256 per block) + softmax(59) + split depth/context
// One block per (b,n,h) row: 384 blocks, 224 threads, 48KB dynamic smem.
// Register tile: 8 outputs x 4 w's per thread (198 active compute threads).
// ============================================================================
__global__ __launch_bounds__(224) void conv_softmax_kernel(
    const float* __restrict__ img, const float* __restrict__ wd,
    const float* __restrict__ bd)
{
    extern __shared__ float sm[];
    float* ws = sm;                 // [64][WSROW] weight chunk (transposed c-major)
    float* xs = sm + 64 * WSROW;    // [64][44]    input chunk

    const int tid = threadIdx.x;
    const int row = blockIdx.x;             // bn*16 + h
    const int bn  = row >> 4;
    const int h   = row & 15;
    const float* src = img + (size_t)bn * CIN * HW + h * W_;
    const float4* w4 = (const float4*)wd;   // [139][64] float4

    const int wt = tid % 11;   // w-tile (4 w's)
    const int ot = tid / 11;   // o-tile (8 o's), valid for tid < 198

    float acc[8][4];
#pragma unroll
    for (int j = 0; j < 8; j++)
#pragma unroll
        for (int k = 0; k < 4; k++) acc[j][k] = 0.f;

    for (int ck = 0; ck < 4; ck++) {        // 4 chunks of 64 input channels
        __syncthreads();
        // load weight chunk, transposed into [c][o] with padded rows
        for (int i = tid; i < O_TOT * 16; i += 224) {
            int o  = i >> 4;
            int c4 = i & 15;
            float4 v = w4[o * 64 + ck * 16 + c4];
            int c = c4 * 4;
            ws[(c + 0) * WSROW + o] = v.x;
            ws[(c + 1) * WSROW + o] = v.y;
            ws[(c + 2) * WSROW + o] = v.z;
            ws[(c + 3) * WSROW + o] = v.w;
        }
        // load input chunk [c][w]
        for (int i = tid; i < 64 * W_; i += 224) {
            int c = i / W_;
            int w = i - c * W_;
            xs[i] = src[(ck * 64 + c) * HW + w];
        }
        __syncthreads();

        if (tid < 198) {
#pragma unroll 2
            for (int c = 0; c < 64; c++) {
                float4 xv = *(const float4*)&xs[c * W_ + wt * 4];
                float4 wa = *(const float4*)&ws[c * WSROW + ot * 8];
                float4 wb = *(const float4*)&ws[c * WSROW + ot * 8 + 4];
                float wv[8] = {wa.x, wa.y, wa.z, wa.w, wb.x, wb.y, wb.z, wb.w};
                float xr[4] = {xv.x, xv.y, xv.z, xv.w};
#pragma unroll
                for (int j = 0; j < 8; j++)
#pragma unroll
                    for (int k = 0; k < 4; k++) acc[j][k] += wv[j] * xr[k];
            }
        }
    }

    __syncthreads();
    // dump x (+bias) to smem for cross-thread softmax; reuse smem
    float* xo = sm;   // [o][44], o < 139 used (6336 floats <= 12288 avail)
    if (tid < 198) {
#pragma unroll
        for (int j = 0; j < 8; j++) {
            int o = ot * 8 + j;
            if (o < O_TOT) {
                float bias = __ldg(&bd[o]);
#pragma unroll
                for (int k = 0; k < 4; k++)
                    xo[o * W_ + wt * 4 + k] = acc[j][k] + bias;
            }
        }
    }
    __syncthreads();

    // softmax over first 59 channels per pixel; one warp per column
    const int warp = tid >> 5;
    const int lane = tid & 31;
    const int pixbase = row * W_;
    for (int w = warp; w < W_; w += 7) {
        float v0 = (lane < D_BINS)        ? xo[lane * W_ + w]        : -1e30f;
        float v1 = ((lane + 32) < D_BINS) ? xo[(lane + 32) * W_ + w] : -1e30f;
        float m = fmaxf(v0, v1);
#pragma unroll
        for (int off = 16; off; off >>= 1)
            m = fmaxf(m, __shfl_xor_sync(0xffffffffu, m, off));
        float e0 = (lane < D_BINS)        ? expf(v0 - m) : 0.f;
        float e1 = ((lane + 32) < D_BINS) ? expf(v1 - m) : 0.f;
        float s = e0 + e1;
#pragma unroll
        for (int off = 16; off; off >>= 1)
            s += __shfl_xor_sync(0xffffffffu, s, off);
        float inv = 1.0f / s;
        int pix = pixbase + w;
        if (lane < D_BINS)        g_depth[pix * D_BINS + lane]      = e0 * inv;
        if ((lane + 32) < D_BINS) g_depth[pix * D_BINS + lane + 32] = e1 * inv;
        for (int j = lane; j < C_CH; j += 32)
            g_ctx[pix * C_CH + j] = xo[(D_BINS + j) * W_ + w];
    }
}

// ============================================================================
// K0: zero the scratch BEV (must happen every launch; graph replays)
// ============================================================================
__global__ void zero_bev_kernel()
{
    int i = blockIdx.x * blockDim.x + threadIdx.x;
    if (i < B_ * BEV_HW * (C_CH / 4))
        g_bev[i] = make_float4(0.f, 0.f, 0.f, 0.f);
}

// ============================================================================
// K2: scatter-add depth*context into channel-contiguous BEV with red.v4.f32.
// Thread = (point, c4): 16 points per 320-thread block, 20 float4 per point.
// ============================================================================
__global__ __launch_bounds__(320) void scatter_kernel(const int* __restrict__ geom)
{
    const int tid   = threadIdx.x;
    const int pt_in = tid / 20;
    const int c4    = tid - pt_in * 20;
    const int point = blockIdx.x * 16 + pt_in;   // < NPT always (exact grid)

    const int pix = point / D_BINS;
    const int d   = point - pix * D_BINS;
    const int bn  = pix / HW;
    const int hw  = pix - bn * HW;
    const int b   = bn / N_;

    const int gidx = ((bn * D_BINS + d) * HW + hw) * 2;
    const int gy = __ldg(&geom[gidx]);
    const int gx = __ldg(&geom[gidx + 1]);

    const float dep = g_depth[point];
    const float4 ctx = ((const float4*)g_ctx)[pix * 20 + c4];

    float4* dst = &g_bev[(b * BEV_HW + gy * BEVW + gx) * 20 + c4];
    float vx = dep * ctx.x, vy = dep * ctx.y, vz = dep * ctx.z, vw = dep * ctx.w;
    asm volatile("red.global.add.v4.f32 [%0], {%1,%2,%3,%4};"
                 :: "l"(dst), "f"(vx), "f"(vy), "f"(vz), "f"(vw)
                 : "memory");
}

// ============================================================================
// K3: transpose [b][y][x][c] -> [b][c][y][x], smem-tiled, fully coalesced
// ============================================================================
__global__ __launch_bounds__(256) void transpose_kernel(float* __restrict__ out)
{
    __shared__ float t[32 * 81];   // padded rows: conflict-free
    const int chunk = blockIdx.x;        // b*512 + yx-chunk
    const int b   = chunk >> 9;
    const int yx0 = (chunk & 511) * 32;

    const float* srcp = (const float*)g_bev + ((size_t)b * BEV_HW + yx0) * C_CH;
    for (int i = threadIdx.x; i < 32 * C_CH; i += 256) {
        int j = i / C_CH;
        int c = i - j * C_CH;
        t[j * 81 + c] = srcp[i];         // linear coalesced read
    }
    __syncthreads();

    float* dst = out + (size_t)b * C_CH * BEV_HW + yx0;
    for (int i = threadIdx.x; i < 32 * C_CH; i += 256) {
        int c = i >> 5;
        int j = i & 31;
        dst[c * BEV_HW + j] = t[j * 81 + c];   // 128B coalesced writes
    }
}

// ============================================================================
extern "C" void kernel_launch(void* const* d_in, const int* in_sizes, int n_in,
                              void* d_out, int out_size)
{
    const float* img  = (const float*)d_in[0];
    const float* wd   = (const float*)d_in[4];
    const float* bd   = (const float*)d_in[5];
    const int*   geom = (const int*)d_in[6];
    float* out = (float*)d_out;

    conv_softmax_kernel<<<B_ * N_ * H_, 224, 64 * WSROW * 4 + 64 * W_ * 4>>>(img, wd, bd);
    zero_bev_kernel<<<(B_ * BEV_HW * (C_CH / 4) + 255) / 256, 256>>>();
    scatter_kernel<<<NPT / 16, 320>>>(geom);
    transpose_kernel<<<B_ * (BEV_HW / 32), 256>>>(out);
}

// round 2
// speedup vs baseline: 1.0321x; 1.0321x over previous
#include <cuda_runtime.h>
#include <cstdint>

#define D_BINS 59
#define C_CH   80
#define O_TOT  139
#define WSROW  148   // padded smem row for weights
#define B_     4
#define N_     6
#define CIN    256
#define H_     16
#define W_     44
#define HW     704              // H_*W_
#define NPIX   (B_*N_*H_*W_)    // 16896
#define NPT    (NPIX*D_BINS)    // 996864
#define BEV_HW 16384
#define BEVW   128
#define NPAIR  (D_BINS*W_)      // 2596 (d,w) pairs per block

// ---- device scratch (no allocations allowed) ----
__device__ float4 g_bev[B_*BEV_HW*(C_CH/4)];  // [b][y][x][c4] ~21 MB (L2-resident)

// ============================================================================
// K0: zero the scratch BEV (graph replays -> must re-zero every launch)
// ============================================================================
__global__ void zero_bev_kernel()
{
    int i = blockIdx.x * blockDim.x + threadIdx.x;
    if (i < B_ * BEV_HW * (C_CH / 4))
        g_bev[i] = make_float4(0.f, 0.f, 0.f, 0.f);
}

// ============================================================================
// K1: FUSED conv(139x44x256) + softmax(59) + scatter(red.v4 into BEV scratch)
// One block per (b,n,h) row: 384 blocks, 224 threads, 48KB dynamic smem.
// Phases: [GEMM regs] -> [dump logits/ctx to smem + stage geom cells]
//         -> [softmax] -> [smem-sourced red.global.add.v4]
// ============================================================================
__global__ __launch_bounds__(224) void fused_kernel(
    const float* __restrict__ img, const float* __restrict__ wd,
    const float* __restrict__ bd,  const int*   __restrict__ geom)
{
    extern __shared__ float sm[];
    // compute-phase layout
    float* ws = sm;                 // [64][WSROW] weight chunk (c-major)
    float* xs = sm + 64 * WSROW;    // [64][44]    input chunk   (ends at 12288 floats)
    // scatter-phase layout (reused after syncs; all fit in 48KB)
    float* xo_d   = sm;                    // [59][44] depth logits   (2596)
    float* s_dep  = sm + NPAIR;            // [59][44] softmaxed      (2596)
    float* s_ctx  = sm + 2 * NPAIR;        // [44][80] context        (3520, 16B-aligned)
    int*   s_cell = (int*)(sm + 2 * NPAIR + W_ * C_CH);  // [59][44]  (2596)

    const int tid = threadIdx.x;
    const int row = blockIdx.x;             // bn*16 + h
    const int bn  = row >> 4;
    const int h   = row & 15;
    const int b   = bn / N_;
    const float* src = img + (size_t)bn * CIN * HW + h * W_;
    const float4* w4 = (const float4*)wd;   // [139][64] float4

    const int wt = tid % 11;   // w-tile (4 w's)
    const int ot = tid / 11;   // o-tile (8 o's), valid for tid < 198

    float acc[8][4];
#pragma unroll
    for (int j = 0; j < 8; j++)
#pragma unroll
        for (int k = 0; k < 4; k++) acc[j][k] = 0.f;

    // ---------------- GEMM: 4 chunks of 64 input channels ----------------
    for (int ck = 0; ck < 4; ck++) {
        __syncthreads();
        for (int i = tid; i < O_TOT * 16; i += 224) {
            int o  = i >> 4;
            int c4 = i & 15;
            float4 v = w4[o * 64 + ck * 16 + c4];
            int c = c4 * 4;
            ws[(c + 0) * WSROW + o] = v.x;
            ws[(c + 1) * WSROW + o] = v.y;
            ws[(c + 2) * WSROW + o] = v.z;
            ws[(c + 3) * WSROW + o] = v.w;
        }
        for (int i = tid; i < 64 * W_; i += 224) {
            int c = i / W_;
            int w = i - c * W_;
            xs[i] = src[(ck * 64 + c) * HW + w];
        }
        __syncthreads();

        if (tid < 198) {
#pragma unroll 2
            for (int c = 0; c < 64; c++) {
                float4 xv = *(const float4*)&xs[c * W_ + wt * 4];
                float4 wa = *(const float4*)&ws[c * WSROW + ot * 8];
                float4 wb = *(const float4*)&ws[c * WSROW + ot * 8 + 4];
                float wv[8] = {wa.x, wa.y, wa.z, wa.w, wb.x, wb.y, wb.z, wb.w};
                float xr[4] = {xv.x, xv.y, xv.z, xv.w};
#pragma unroll
                for (int j = 0; j < 8; j++)
#pragma unroll
                    for (int k = 0; k < 4; k++) acc[j][k] += wv[j] * xr[k];
            }
        }
    }

    __syncthreads();
    // ------- dump: depth logits -> xo_d[o][w]; context -> s_ctx[w][c] -------
    if (tid < 198) {
#pragma unroll
        for (int j = 0; j < 8; j++) {
            int o = ot * 8 + j;
            if (o < O_TOT) {
                float bias = __ldg(&bd[o]);
#pragma unroll
                for (int k = 0; k < 4; k++) {
                    int w = wt * 4 + k;
                    float v = acc[j][k] + bias;
                    if (o < D_BINS) xo_d[o * W_ + w] = v;
                    else            s_ctx[w * C_CH + (o - D_BINS)] = v;
                }
            }
        }
    }
    // ------- stage geom cells (global latency overlapped with dump) -------
    {
        const int2* g2 = (const int2*)geom;
        const int cbase = bn * D_BINS * HW + h * W_;
        for (int i = tid; i < NPAIR; i += 224) {
            int d = i / W_;
            int w = i - d * W_;
            int2 g = __ldg(&g2[cbase + d * HW + w]);
            s_cell[i] = (b << 14) + g.x * BEVW + g.y;
        }
    }
    __syncthreads();

    // ---------------- softmax over 59 bins; one warp per column ----------------
    const int warp = tid >> 5;
    const int lane = tid & 31;
    for (int w = warp; w < W_; w += 7) {
        float v0 = (lane < D_BINS)        ? xo_d[lane * W_ + w]        : -1e30f;
        float v1 = ((lane + 32) < D_BINS) ? xo_d[(lane + 32) * W_ + w] : -1e30f;
        float m = fmaxf(v0, v1);
#pragma unroll
        for (int off = 16; off; off >>= 1)
            m = fmaxf(m, __shfl_xor_sync(0xffffffffu, m, off));
        float e0 = (lane < D_BINS)        ? expf(v0 - m) : 0.f;
        float e1 = ((lane + 32) < D_BINS) ? expf(v1 - m) : 0.f;
        float s = e0 + e1;
#pragma unroll
        for (int off = 16; off; off >>= 1)
            s += __shfl_xor_sync(0xffffffffu, s, off);
        float inv = 1.0f / s;
        if (lane < D_BINS)        s_dep[lane * W_ + w]        = e0 * inv;
        if ((lane + 32) < D_BINS) s_dep[(lane + 32) * W_ + w] = e1 * inv;
    }
    __syncthreads();

    // ---------------- scatter: red.global.add.v4 from smem ----------------
    if (tid < 220) {
        const int c4  = tid % 20;
        const int grp = tid / 20;          // 0..10, NPAIR/11 = 236 iters each
        int w = grp;                       // p = grp -> d=0, w=grp (grp < 44)
        for (int p = grp; p < NPAIR; p += 11) {
            int   cell = s_cell[p];
            float dep  = s_dep[p];
            float4 cv  = *(const float4*)&s_ctx[w * C_CH + c4 * 4];
            float4* dst = &g_bev[cell * 20 + c4];
            asm volatile("red.global.add.v4.f32 [%0], {%1,%2,%3,%4};"
                         :: "l"(dst), "f"(dep * cv.x), "f"(dep * cv.y),
                            "f"(dep * cv.z), "f"(dep * cv.w)
                         : "memory");
            w += 11; if (w >= W_) w -= W_;
        }
    }
}

// ============================================================================
// K2: transpose [b][y][x][c] -> [b][c][y][x].
// 128 yx x 80 c tile per block; float4 reads, 128B-coalesced warp writes,
// smem row pad 81 (lane*81 mod 32 cycles all banks -> conflict-free reads).
// ============================================================================
__global__ __launch_bounds__(256) void transpose_kernel(float* __restrict__ out)
{
    __shared__ float t[128 * 81];   // 41.5 KB
    const int chunk = blockIdx.x;        // b*128 + yx-chunk
    const int b   = chunk >> 7;
    const int yx0 = (chunk & 127) * 128;

    const float4* src = (const float4*)g_bev + ((size_t)b * BEV_HW + yx0) * 20;
#pragma unroll
    for (int i = threadIdx.x; i < 128 * 20; i += 256) {
        int yx = i / 20;
        int c4 = i - yx * 20;
        float4 v = src[i];
        float* tp = &t[yx * 81 + c4 * 4];
        tp[0] = v.x; tp[1] = v.y; tp[2] = v.z; tp[3] = v.w;
    }
    __syncthreads();

    float* dst = out + ((size_t)b * C_CH) * BEV_HW + yx0;
#pragma unroll
    for (int i = threadIdx.x; i < 128 * C_CH; i += 256) {
        int c  = i >> 7;
        int yx = i & 127;
        dst[(size_t)c * BEV_HW + yx] = t[yx * 81 + c];
    }
}

// ============================================================================
extern "C" void kernel_launch(void* const* d_in, const int* in_sizes, int n_in,
                              void* d_out, int out_size)
{
    const float* img  = (const float*)d_in[0];
    const float* wd   = (const float*)d_in[4];
    const float* bd   = (const float*)d_in[5];
    const int*   geom = (const int*)d_in[6];
    float* out = (float*)d_out;

    zero_bev_kernel<<<(B_ * BEV_HW * (C_CH / 4) + 255) / 256, 256>>>();
    fused_kernel<<<B_ * N_ * H_, 224, (64 * WSROW + 64 * W_) * 4>>>(img, wd, bd, geom);
    transpose_kernel<<<B_ * (BEV_HW / 128), 256>>>(out);
}

// round 3
// speedup vs baseline: 1.1419x; 1.1064x over previous
#include <cuda_runtime.h>
#include <cstdint>

#define D_BINS 59
#define C_CH   80
#define O_TOT  139
#define WSROW  148   // padded smem row for weights
#define B_     4
#define N_     6
#define CIN    256
#define H_     16
#define W_     44
#define HW     704              // H_*W_
#define NPIX   (B_*N_*H_*W_)    // 16896
#define NCELL  (B_*128*128)     // 65536
#define BEVW   128
#define NPAIR  (D_BINS*W_)      // 2596 (d,w) pairs per conv block
#define CAP    64               // bin capacity per cell (mean 15.2, P(>=64)~1e-18)

// ---- device scratch (no allocations allowed) ----
__device__ float g_ctx[NPIX*C_CH];        // [pix][c]  5.4 MB (L2-resident)
__device__ int   g_cnt[NCELL];            // per-cell point counts
__device__ int2  g_bin[NCELL*CAP];        // {pix, depth-bits} records, 33.5 MB

// ============================================================================
// K0: zero the cell counters (graph replays -> must re-zero every launch)
// ============================================================================
__global__ void zero_cnt_kernel()
{
    int i = blockIdx.x * blockDim.x + threadIdx.x;
    ((int4*)g_cnt)[i] = make_int4(0, 0, 0, 0);   // grid covers exactly NCELL/4
}

// ============================================================================
// K1: FUSED conv(139x44x256) + softmax(59) + ctx store + cell binning.
// One block per (b,n,h) row: 384 blocks, 224 threads, 48KB dynamic smem.
// ============================================================================
__global__ __launch_bounds__(224) void conv_bin_kernel(
    const float* __restrict__ img, const float* __restrict__ wd,
    const float* __restrict__ bd,  const int*   __restrict__ geom)
{
    extern __shared__ float sm[];
    // compute-phase layout
    float* ws = sm;                 // [64][WSROW] weight chunk (c-major)
    float* xs = sm + 64 * WSROW;    // [64][44]    input chunk (total 12288 floats)
    // post-GEMM layout (reused after syncs)
    float* xo_d   = sm;                    // [59][44] depth logits   (2596)
    float* s_dep  = sm + NPAIR;            // [59][44] softmaxed      (2596)
    float* s_ctx  = sm + 2 * NPAIR;        // [44][80] context        (3520, 16B-aligned)
    int*   s_cell = (int*)(sm + 2 * NPAIR + W_ * C_CH);  // [59][44]  (2596)

    const int tid = threadIdx.x;
    const int row = blockIdx.x;             // bn*16 + h
    const int bn  = row >> 4;
    const int h   = row & 15;
    const int b   = bn / N_;
    const float* src = img + (size_t)bn * CIN * HW + h * W_;
    const float4* w4 = (const float4*)wd;   // [139][64] float4

    const int wt = tid % 11;   // w-tile (4 w's)
    const int ot = tid / 11;   // o-tile (8 o's), valid for tid < 198

    float acc[8][4];
#pragma unroll
    for (int j = 0; j < 8; j++)
#pragma unroll
        for (int k = 0; k < 4; k++) acc[j][k] = 0.f;

    // ---------------- GEMM: 4 chunks of 64 input channels ----------------
    for (int ck = 0; ck < 4; ck++) {
        __syncthreads();
        for (int i = tid; i < O_TOT * 16; i += 224) {
            int o  = i >> 4;
            int c4 = i & 15;
            float4 v = w4[o * 64 + ck * 16 + c4];
            int c = c4 * 4;
            ws[(c + 0) * WSROW + o] = v.x;
            ws[(c + 1) * WSROW + o] = v.y;
            ws[(c + 2) * WSROW + o] = v.z;
            ws[(c + 3) * WSROW + o] = v.w;
        }
        for (int i = tid; i < 64 * W_; i += 224) {
            int c = i / W_;
            int w = i - c * W_;
            xs[i] = src[(ck * 64 + c) * HW + w];
        }
        __syncthreads();

        if (tid < 198) {
#pragma unroll 2
            for (int c = 0; c < 64; c++) {
                float4 xv = *(const float4*)&xs[c * W_ + wt * 4];
                float4 wa = *(const float4*)&ws[c * WSROW + ot * 8];
                float4 wb = *(const float4*)&ws[c * WSROW + ot * 8 + 4];
                float wv[8] = {wa.x, wa.y, wa.z, wa.w, wb.x, wb.y, wb.z, wb.w};
                float xr[4] = {xv.x, xv.y, xv.z, xv.w};
#pragma unroll
                for (int j = 0; j < 8; j++)
#pragma unroll
                    for (int k = 0; k < 4; k++) acc[j][k] += wv[j] * xr[k];
            }
        }
    }

    __syncthreads();
    // ------- dump: depth logits -> xo_d[d][w]; context -> s_ctx[w][c] -------
    if (tid < 198) {
#pragma unroll
        for (int j = 0; j < 8; j++) {
            int o = ot * 8 + j;
            if (o < O_TOT) {
                float bias = __ldg(&bd[o]);
#pragma unroll
                for (int k = 0; k < 4; k++) {
                    int w = wt * 4 + k;
                    float v = acc[j][k] + bias;
                    if (o < D_BINS) xo_d[o * W_ + w] = v;
                    else            s_ctx[w * C_CH + (o - D_BINS)] = v;
                }
            }
        }
    }
    // ------- stage geom cells (global latency overlapped with dump) -------
    {
        const int2* g2 = (const int2*)geom;
        const int cbase = bn * D_BINS * HW + h * W_;
        for (int i = tid; i < NPAIR; i += 224) {
            int d = i / W_;
            int w = i - d * W_;
            int2 g = __ldg(&g2[cbase + d * HW + w]);
            s_cell[i] = (b << 14) + g.x * BEVW + g.y;
        }
    }
    __syncthreads();

    // ------- store context to global (fire-and-forget, overlaps softmax) -------
    {
        const float4* cs = (const float4*)s_ctx;
        float4* cg = (float4*)g_ctx + (size_t)row * W_ * (C_CH / 4);
        for (int i = tid; i < W_ * (C_CH / 4); i += 224)
            cg[i] = cs[i];
    }

    // ---------------- softmax over 59 bins; one warp per column ----------------
    const int warp = tid >> 5;
    const int lane = tid & 31;
    for (int w = warp; w < W_; w += 7) {
        float v0 = (lane < D_BINS)        ? xo_d[lane * W_ + w]        : -1e30f;
        float v1 = ((lane + 32) < D_BINS) ? xo_d[(lane + 32) * W_ + w] : -1e30f;
        float m = fmaxf(v0, v1);
#pragma unroll
        for (int off = 16; off; off >>= 1)
            m = fmaxf(m, __shfl_xor_sync(0xffffffffu, m, off));
        float e0 = (lane < D_BINS)        ? expf(v0 - m) : 0.f;
        float e1 = ((lane + 32) < D_BINS) ? expf(v1 - m) : 0.f;
        float s = e0 + e1;
#pragma unroll
        for (int off = 16; off; off >>= 1)
            s += __shfl_xor_sync(0xffffffffu, s, off);
        float inv = 1.0f / s;
        if (lane < D_BINS)        s_dep[lane * W_ + w]        = e0 * inv;
        if ((lane + 32) < D_BINS) s_dep[(lane + 32) * W_ + w] = e1 * inv;
    }
    __syncthreads();

    // ------- bin the 2596 points: slot = atomicAdd(cnt), write {pix, dep} -------
    const int pixbase = row * W_;
    for (int p = tid; p < NPAIR; p += 224) {
        int w = p % W_;
        int cell = s_cell[p];
        int slot = atomicAdd(&g_cnt[cell], 1);
        if (slot < CAP)
            g_bin[cell * CAP + slot] =
                make_int2(pixbase + w, __float_as_int(s_dep[p]));
    }
}

// ============================================================================
// K2: GATHER per BEV cell + transposed coalesced write of the output.
// 1024 blocks x 256 threads; block = 64 consecutive cells, warp = 8 cells.
// Per point: lanes 0..19 load ctx float4 (coalesced 320B), acc 4ch in regs.
// ============================================================================
__global__ __launch_bounds__(256) void gather_kernel(float* __restrict__ out)
{
    __shared__ float t[C_CH * 65];   // [c][64+1 pad] 20.8 KB, conflict-free
    const int b     = blockIdx.x >> 8;
    const int yx0   = (blockIdx.x & 255) * 64;
    const int warp  = threadIdx.x >> 5;
    const int lane  = threadIdx.x & 31;
    const float4* ctx4 = (const float4*)g_ctx;

#pragma unroll
    for (int cc = 0; cc < 8; cc++) {
        const int cl   = warp * 8 + cc;          // local cell 0..63
        const int cell = (b << 14) + yx0 + cl;
        int cnt = g_cnt[cell];
        if (cnt > CAP) cnt = CAP;

        float4 acc = make_float4(0.f, 0.f, 0.f, 0.f);
        const int2* rec = &g_bin[cell * CAP];
        for (int pt = 0; pt < cnt; pt++) {
            int2 r = rec[pt];                    // broadcast load (1 sector)
            float dep = __int_as_float(r.y);
            if (lane < 20) {
                float4 cv = __ldg(&ctx4[r.x * 20 + lane]);
                acc.x += dep * cv.x;
                acc.y += dep * cv.y;
                acc.z += dep * cv.z;
                acc.w += dep * cv.w;
            }
        }
        if (lane < 20) {
            int c = lane * 4;
            t[(c + 0) * 65 + cl] = acc.x;
            t[(c + 1) * 65 + cl] = acc.y;
            t[(c + 2) * 65 + cl] = acc.z;
            t[(c + 3) * 65 + cl] = acc.w;
        }
    }
    __syncthreads();

    float* dst = out + ((size_t)b * C_CH) * (128 * 128) + yx0;
#pragma unroll
    for (int i = threadIdx.x; i < C_CH * 64; i += 256) {
        int c = i >> 6;
        int j = i & 63;
        dst[(size_t)c * (128 * 128) + j] = t[c * 65 + j];
    }
}

// ============================================================================
extern "C" void kernel_launch(void* const* d_in, const int* in_sizes, int n_in,
                              void* d_out, int out_size)
{
    const float* img  = (const float*)d_in[0];
    const float* wd   = (const float*)d_in[4];
    const float* bd   = (const float*)d_in[5];
    const int*   geom = (const int*)d_in[6];
    float* out = (float*)d_out;

    zero_cnt_kernel<<<NCELL / 4 / 256, 256>>>();
    conv_bin_kernel<<<B_ * N_ * H_, 224, (64 * WSROW + 64 * W_) * 4>>>(img, wd, bd, geom);
    gather_kernel<<<B_ * 256, 256>>>(out);
}